// round 17
// baseline (speedup 1.0000x reference)
#include <cuda_runtime.h>
#include <cstdint>

// Problem constants
#define NQ   20
#define NL   8
#define BB   32
#define DIM  (1u << NQ)        // 1048576
#define NF4  (DIM / 4)         // 262144 float4s per statevector
#define TPB  256

// Fused geometry: 32 chunks x 16 batch-groups (2 batches each) = 512 blocks
#define CHUNKS 32
#define BPG 2
#define NGRP (BB / BPG)                // 16
#define F4_PER_CHUNK (NF4 / CHUNKS)    // 8192
#define NIT 32                         // NIT*TPB == F4_PER_CHUNK; 8 j4-groups

// Scratch: G stored as bf16 (uint2 = 4 values); producer-consumer counters
__device__ uint2    g_Gh[NF4];
__device__ float    g_part[CHUNKS * NGRP * BPG * 21];
__device__ unsigned g_cnt[CHUNKS][8];          // zero-init; reset by k_final

// ---- packed f32x2 helpers ----
__device__ __forceinline__ uint64_t mulx2(uint64_t a, uint64_t b) {
    uint64_t r; asm("mul.rn.f32x2 %0,%1,%2;" : "=l"(r) : "l"(a), "l"(b)); return r;
}
__device__ __forceinline__ uint64_t addx2(uint64_t a, uint64_t b) {
    uint64_t r; asm("add.rn.f32x2 %0,%1,%2;" : "=l"(r) : "l"(a), "l"(b)); return r;
}
__device__ __forceinline__ uint64_t fmx2(uint64_t a, uint64_t b, uint64_t c) {
    uint64_t r; asm("fma.rn.f32x2 %0,%1,%2,%3;" : "=l"(r) : "l"(a), "l"(b), "l"(c)); return r;
}
__device__ __forceinline__ float lo32(uint64_t v) { return __uint_as_float((unsigned)v); }
__device__ __forceinline__ float hi32(uint64_t v) { return __uint_as_float((unsigned)(v >> 32)); }

__device__ __forceinline__ uint64_t bf2_to_f32x2(uint32_t p) {
    uint32_t lo, hi;
    asm("prmt.b32 %0, %1, 0, 0x1044;" : "=r"(lo) : "r"(p));
    asm("prmt.b32 %0, %1, 0, 0x3244;" : "=r"(hi) : "r"(p));
    uint64_t r; asm("mov.b64 %0, {%1,%2};" : "=l"(r) : "r"(lo), "r"(hi));
    return r;
}
__device__ __forceinline__ unsigned ld_acq(const unsigned* p) {
    unsigned v;
    asm volatile("ld.global.acquire.gpu.u32 %0, [%1];" : "=r"(v) : "l"(p) : "memory");
    return v;
}

union F4U2 { uint4 u; ulonglong2 l; };

// ---------------------------------------------------------------------------
// Fused kernel: each block first PRODUCES 1/16 of its chunk's G (64KB noise),
// publishes via release-counter, then runs the bit-masked reduction, gating
// each j4-group on its counter. 512 blocks = one wave -> spin-safe.
// ---------------------------------------------------------------------------
__global__ void __launch_bounds__(TPB, 4) k_fused(const float* __restrict__ noise,
                                                  const float* __restrict__ amps) {
    const int bg    = blockIdx.x & (NGRP - 1);
    const int chunk = blockIdx.x >> 4;
    const int t     = threadIdx.x;

    // ---- Phase 1: produce G for (group = bg>>1, half = bg&1) of this chunk ----
    {
        const int group = bg >> 1, half = bg & 1;
        const unsigned pbase = chunk * F4_PER_CHUNK + group * 1024 + half * 512 + t;
        const float4* n4 = reinterpret_cast<const float4*>(noise);
#pragma unroll
        for (int u = 0; u < 2; u++) {
            const unsigned idx = pbase + u * 256;
            float4 v = __ldcs(n4 + idx);
            float4 g;
            g.x = v.x * v.x; g.y = v.y * v.y; g.z = v.z * v.z; g.w = v.w * v.w;
#pragma unroll
            for (int l = 1; l < NL; l++) {
                v = __ldcs(n4 + (size_t)l * NF4 + idx);
                g.x *= v.x * v.x; g.y *= v.y * v.y;
                g.z *= v.z * v.z; g.w *= v.w * v.w;
            }
            uint2 p;
            asm("cvt.rn.bf16x2.f32 %0, %1, %2;" : "=r"(p.x) : "f"(g.y), "f"(g.x));
            asm("cvt.rn.bf16x2.f32 %0, %1, %2;" : "=r"(p.y) : "f"(g.w), "f"(g.z));
            g_Gh[idx] = p;
        }
        __threadfence();                       // release G stores
        __syncthreads();
        if (t == 0) atomicAdd(&g_cnt[chunk][group], 1u);
    }

    // ---- Phase 2: bit-masked reduction (R15 math, gated per j4-group) ----
    const size_t sliceOff = (size_t)chunk * F4_PER_CHUNK + t;
    const uint2* g2   = g_Gh + sliceOff;
    const uint4* a4_0 = reinterpret_cast<const uint4*>(amps)
                        + (size_t)(bg * BPG + 0) * NF4 + sliceOff;
    const uint4* a4_1 = reinterpret_cast<const uint4*>(amps)
                        + (size_t)(bg * BPG + 1) * NF4 + sliceOff;

    uint64_t T01[BPG] = {0, 0}, T23[BPG] = {0, 0};
    uint64_t J0[BPG] = {0, 0}, J1[BPG] = {0, 0}, J2[BPG] = {0, 0},
             J3[BPG] = {0, 0}, J4[BPG] = {0, 0};

#pragma unroll
    for (int j4 = 0; j4 < NIT / 4; j4++) {
        // gate: wait until both producers of this j4-group have published
        if (t == 0) {
            while (ld_acq(&g_cnt[chunk][j4]) < 2u) {}
        }
        __syncthreads();

        uint64_t sp[4][BPG];
#pragma unroll
        for (int jj = 0; jj < 4; jj++) {
            const int off = (j4 * 4 + jj) * TPB;
            uint2 gh = __ldg(g2 + off);                   // L2-hot
            uint64_t gx01 = bf2_to_f32x2(gh.x);
            uint64_t gx23 = bf2_to_f32x2(gh.y);
            F4U2 A0, A1;
            A0.u = __ldcs(a4_0 + off);                    // streaming
            A1.u = __ldcs(a4_1 + off);
#pragma unroll
            for (int b2 = 0; b2 < BPG; b2++) {
                uint64_t a01 = b2 ? A1.l.x : A0.l.x;
                uint64_t a23 = b2 ? A1.l.y : A0.l.y;
                uint64_t t01 = mulx2(a01, a01);
                uint64_t t23 = mulx2(a23, a23);
                uint64_t w23 = mulx2(t23, gx23);
                sp[jj][b2]  = fmx2(t01, gx01, w23);       // (w0+w2, w1+w3)
                T01[b2] = fmx2(t01, gx01, T01[b2]);
                T23[b2] = addx2(T23[b2], w23);
            }
        }
#pragma unroll
        for (int b2 = 0; b2 < BPG; b2++) {
            J0[b2] = addx2(J0[b2], addx2(sp[1][b2], sp[3][b2]));   // qubit 10
            uint64_t P0 = addx2(sp[0][b2], sp[1][b2]);
            uint64_t P1 = addx2(sp[2][b2], sp[3][b2]);
            J1[b2] = addx2(J1[b2], P1);                            // qubit 11
            uint64_t Q = addx2(P0, P1);
            if (j4 & 1) J2[b2] = addx2(J2[b2], Q);                 // qubit 12
            if (j4 & 2) J3[b2] = addx2(J3[b2], Q);                 // qubit 13
            if (j4 & 4) J4[b2] = addx2(J4[b2], Q);                 // qubit 14
        }
    }

    __shared__ float sT[BPG][TPB];
    __shared__ float red[TPB / 32][BPG][7];
    const int wid = t >> 5, lane = t & 31;

#pragma unroll
    for (int b2 = 0; b2 < BPG; b2++) {
        float S0 = lo32(T01[b2]), S1 = hi32(T01[b2]);
        float S2 = lo32(T23[b2]), S3 = hi32(T23[b2]);
        float v[7];
        v[0] = S1 + S3;                                   // qubit 0
        v[1] = S2 + S3;                                   // qubit 1
        v[2] = lo32(J0[b2]) + hi32(J0[b2]);
        v[3] = lo32(J1[b2]) + hi32(J1[b2]);
        v[4] = lo32(J2[b2]) + hi32(J2[b2]);
        v[5] = lo32(J3[b2]) + hi32(J3[b2]);
        v[6] = lo32(J4[b2]) + hi32(J4[b2]);
        sT[b2][t] = (S0 + S1) + (S2 + S3);
#pragma unroll
        for (int k = 0; k < 7; k++) {
#pragma unroll
            for (int o = 16; o > 0; o >>= 1)
                v[k] += __shfl_xor_sync(0xffffffffu, v[k], o);
        }
        if (lane == 0) {
#pragma unroll
            for (int k = 0; k < 7; k++) red[wid][b2][k] = v[k];
        }
    }
    __syncthreads();

    if (wid < BPG) {
        const int b2 = wid;
        float v[8];
#pragma unroll
        for (int k = 0; k < 8; k++) v[k] = sT[b2][lane + 32 * k];
        float tt = ((v[0] + v[1]) + (v[2] + v[3])) + ((v[4] + v[5]) + (v[6] + v[7]));
        float m[8];
        m[5] = (v[1] + v[3]) + (v[5] + v[7]);             // qubit 7
        m[6] = (v[2] + v[3]) + (v[6] + v[7]);             // qubit 8
        m[7] = (v[4] + v[5]) + (v[6] + v[7]);             // qubit 9
#pragma unroll
        for (int k = 0; k < 5; k++)
            m[k] = ((lane >> k) & 1) ? tt : 0.f;          // qubits 2..6
#pragma unroll
        for (int o = 16; o > 0; o >>= 1) {
            tt += __shfl_xor_sync(0xffffffffu, tt, o);
#pragma unroll
            for (int k = 0; k < 8; k++)
                m[k] += __shfl_xor_sync(0xffffffffu, m[k], o);
        }
        if (lane == 0) {
            float q[21];
#pragma unroll
            for (int k = 0; k < 7; k++) {
                float s = 0.f;
#pragma unroll
                for (int w = 0; w < TPB / 32; w++) s += red[w][b2][k];
                q[(k < 2) ? k : (8 + k)] = s;             // q0,q1, q10..q14
            }
#pragma unroll
            for (int k = 0; k < 8; k++) q[2 + k] = m[k];  // qubits 2..9
#pragma unroll
            for (int k = 0; k < 5; k++)
                q[15 + k] = ((chunk >> k) & 1) ? tt : 0.f;
            q[20] = tt;
            float* dst = &g_part[(size_t)blockIdx.x * (BPG * 21) + b2 * 21];
#pragma unroll
            for (int k = 0; k < 21; k++) dst[k] = q[k];
        }
    }
}

// ---------------------------------------------------------------------------
// Kernel 2: one block per batch, 672 threads, smem tree + matvec.
// Also RESETS the producer counters for the next graph replay.
// ---------------------------------------------------------------------------
__global__ void __launch_bounds__(672) k_final(const float* __restrict__ Wi,
                                               const float* __restrict__ bi,
                                               float* __restrict__ out) {
    const int b  = blockIdx.x;
    const int bg = b >> 1, b2 = b & 1;
    const int t  = threadIdx.x;
    const int c  = t / 21, k = t % 21;

    if (b == 0 && t < CHUNKS * 8)
        g_cnt[t >> 3][t & 7] = 0;            // reset for next execution

    __shared__ float sm[CHUNKS * 21];
    sm[t] = __ldg(&g_part[(size_t)(c * NGRP + bg) * (BPG * 21) + b2 * 21 + k]);
    __syncthreads();

#pragma unroll
    for (int step = CHUNKS / 2; step >= 1; step >>= 1) {
        if (c < step) sm[c * 21 + k] += sm[(c + step) * 21 + k];
        __syncthreads();
    }

    if (t < NQ) {
        const float inv = 1.f / sm[20];
        float acc = bi[t];
#pragma unroll
        for (int q = 0; q < NQ; q++) acc += (sm[q] * inv) * Wi[q * NQ + t];
        out[b * NQ + t] = tanhf(acc);
    }
}

// ---------------------------------------------------------------------------
// Launch: 2 graph-capturable kernels, no syncs, no allocations.
// ---------------------------------------------------------------------------
extern "C" void kernel_launch(void* const* d_in, const int* in_sizes, int n_in,
                              void* d_out, int out_size) {
    int i_amps = 7, i_noise = 8, i_Wi = 9, i_bi = 10;
    for (int i = 0; i < n_in; i++) {
        const long sz = in_sizes[i];
        if (sz == (long)BB * (long)DIM)      i_amps  = i;
        else if (sz == (long)NL * (long)DIM) i_noise = i;
        else if (sz == NQ * NQ)              i_Wi    = i;
        else if (sz == NQ)                   i_bi    = i;
    }

    const float* noise = (const float*)d_in[i_noise];
    const float* amps  = (const float*)d_in[i_amps];
    const float* Wi    = (const float*)d_in[i_Wi];
    const float* bi    = (const float*)d_in[i_bi];
    float* out         = (float*)d_out;

    k_fused<<<CHUNKS * NGRP, TPB>>>(noise, amps);  // 512 blocks, one wave
    k_final<<<BB, 672>>>(Wi, bi, out);             //  32 blocks
}